// round 5
// baseline (speedup 1.0000x reference)
#include <cuda_runtime.h>

#define T 4096
#define H 4096
#define K 8
#define E 64
#define TK (T*K)             // 32768 slots
#define SORTB 64             // sort blocks (blocks 0..63)
#define TPB 2                // tokens per token-block
#define NTOK (T / TPB)       // 2048 token blocks
#define NTOT (NTOK + SORTB)  // total grid

// Scratch (no cudaMalloc allowed)
__device__ int g_rank[TK];            // stable rank within (sortblock, expert)
__device__ int g_blockcount[SORTB*E];
__device__ int g_blockbase[SORTB*E];
__device__ int g_expertbase[E];
__device__ int g_arrive;              // monotonic across replays; use %SORTB
__device__ int g_done;                // monotonic across replays; use %NTOT
__device__ int g_flag;                // 0 at launch start; 1 = sort done; reset by last block

// ---------------------------------------------------------------------------
// One fused kernel. Blocks [0,64): counting sort of the 32768 (token,k) slots
// over 64 experts. Blocks [64,2112): two tokens each. Token blocks do both
// tokens' x-loads + combined writes BEFORE polling the sort flag (≈2x the
// pre-poll traffic of R4 -> sort fully hidden), stashing token A's row in
// smem so both dispatch scatters can run post-flag without re-reading DRAM.
// ---------------------------------------------------------------------------
__global__ void __launch_bounds__(256) k_fused(const float4* __restrict__ x4,
                                               const float*  __restrict__ wts,
                                               const int*    __restrict__ idx,
                                               float4* __restrict__ comb4,
                                               float4* __restrict__ disp4,
                                               float*  __restrict__ tpe) {
    const int tid = threadIdx.x;
    __shared__ float4 stash[1024];     // 16 KB: token A's row (token role)

    if (blockIdx.x < SORTB) {
        // ================= SORT ROLE =================
        __shared__ int whist[8 * E];   // [warp][expert] prefix workspace
        __shared__ int off[E];         // running per-expert offset across chunks
        __shared__ int s_last;
        const int b    = blockIdx.x;
        const int w    = tid >> 5;
        const int lane = tid & 31;

        if (tid < E) off[tid] = 0;

        #pragma unroll
        for (int c = 0; c < 2; c++) {            // 2 chunks of 256 slots
            whist[tid] = 0; whist[tid + 256] = 0;
            __syncthreads();
            const int s = b * 512 + c * 256 + tid;
            const int e = __ldg(&idx[s]);
            unsigned mask = __match_any_sync(0xffffffffu, e);
            const int riw = __popc(mask & ((1u << lane) - 1u));
            if ((__ffs(mask) - 1) == lane) whist[w * E + e] = __popc(mask);
            __syncthreads();
            if (tid < E) {                       // scan 8 warp counts, add chunk offset
                int run = 0;
                #pragma unroll
                for (int ww = 0; ww < 8; ww++) {
                    int cc = whist[ww * E + tid];
                    whist[ww * E + tid] = off[tid] + run;
                    run += cc;
                }
                off[tid] += run;
            }
            __syncthreads();
            g_rank[s] = whist[w * E + e] + riw;
            __syncthreads();                     // protect whist/off for next chunk
        }
        if (tid < E) g_blockcount[b * E + tid] = off[tid];
        __threadfence();
        if (tid == 0) {
            int ticket = atomicAdd(&g_arrive, 1);
            s_last = ((ticket & (SORTB - 1)) == (SORTB - 1));
        }
        __syncthreads();
        if (s_last) {
            // Last-to-arrive block: cross-block + cross-expert scans.
            __threadfence();
            __shared__ int tot[E];
            __shared__ int base[E];
            if (tid < E) {
                int run = 0;
                #pragma unroll
                for (int bb = 0; bb < SORTB; bb++) {
                    int cc = g_blockcount[bb * E + tid];
                    g_blockbase[bb * E + tid] = run;
                    run += cc;
                }
                tot[tid] = run;
            }
            __syncthreads();
            if (tid == 0) {
                int acc = 0;
                #pragma unroll
                for (int i = 0; i < E; i++) { base[i] = acc; acc += tot[i]; }
            }
            __syncthreads();
            if (tid < E) {
                g_expertbase[tid] = base[tid];
                if (tpe) tpe[tid] = (float)tot[tid];
            }
            __threadfence();
            if (tid == 0) atomicExch(&g_flag, 1);
        }
    } else {
        // ================= TOKEN ROLE (2 tokens) =================
        const int tA = (blockIdx.x - SORTB) * TPB;
        const int tB = tA + 1;
        const int ROW4 = H / 4;                  // 1024 float4 per row

        float4 v[4];

        // ---- Token A: load, combined write, stash to smem ----
        #pragma unroll
        for (int i = 0; i < 4; i++)
            v[i] = __ldg(&x4[(size_t)tA * ROW4 + tid + i * 256]);
        {
            float ws = 0.f;
            #pragma unroll
            for (int k = 0; k < K; k++) ws += __ldg(&wts[tA * K + k]);
            if (comb4) {
                #pragma unroll
                for (int i = 0; i < 4; i++) {
                    float4 o = make_float4(v[i].x * ws, v[i].y * ws, v[i].z * ws, v[i].w * ws);
                    __stcs(&comb4[(size_t)tA * ROW4 + tid + i * 256], o);
                }
            }
        }
        #pragma unroll
        for (int i = 0; i < 4; i++) stash[tid + i * 256] = v[i];

        // ---- Token B: load, combined write (keep in regs) ----
        #pragma unroll
        for (int i = 0; i < 4; i++)
            v[i] = __ldg(&x4[(size_t)tB * ROW4 + tid + i * 256]);
        {
            float ws = 0.f;
            #pragma unroll
            for (int k = 0; k < K; k++) ws += __ldg(&wts[tB * K + k]);
            if (comb4) {
                #pragma unroll
                for (int i = 0; i < 4; i++) {
                    float4 o = make_float4(v[i].x * ws, v[i].y * ws, v[i].z * ws, v[i].w * ws);
                    __stcs(&comb4[(size_t)tB * ROW4 + tid + i * 256], o);
                }
            }
        }

        if (disp4) {
            // ---- Wait for sort completion ----
            if (tid == 0) {
                while (*((volatile int*)&g_flag) == 0) __nanosleep(128);
            }
            __syncthreads();
            __threadfence();

            // ---- Dispatch token B (from registers) ----
            int dst[K];
            #pragma unroll
            for (int k = 0; k < K; k++) {
                const int s  = tB * K + k;
                const int bb = s >> 9;           // 512 slots per sort block
                const int e  = idx[s];
                dst[k] = g_expertbase[e] + g_blockbase[bb * E + e] + g_rank[s];
            }
            #pragma unroll
            for (int k = 0; k < K; k++) {
                const size_t basep = (size_t)dst[k] * ROW4;
                #pragma unroll
                for (int i = 0; i < 4; i++)
                    __stcs(&disp4[basep + tid + i * 256], v[i]);
            }

            // ---- Dispatch token A (reload from smem; own slots, no sync) ----
            #pragma unroll
            for (int i = 0; i < 4; i++) v[i] = stash[tid + i * 256];
            #pragma unroll
            for (int k = 0; k < K; k++) {
                const int s  = tA * K + k;
                const int bb = s >> 9;
                const int e  = idx[s];
                dst[k] = g_expertbase[e] + g_blockbase[bb * E + e] + g_rank[s];
            }
            #pragma unroll
            for (int k = 0; k < K; k++) {
                const size_t basep = (size_t)dst[k] * ROW4;
                #pragma unroll
                for (int i = 0; i < 4; i++)
                    __stcs(&disp4[basep + tid + i * 256], v[i]);
            }
        }
    }

    // Epilogue: globally-last block resets g_flag for the next graph replay.
    __syncthreads();
    if (threadIdx.x == 0) {
        __threadfence();
        int d = atomicAdd(&g_done, 1);
        if ((d % NTOT) == (NTOT - 1)) atomicExch(&g_flag, 0);
    }
}

// ---------------------------------------------------------------------------
extern "C" void kernel_launch(void* const* d_in, const int* in_sizes, int n_in,
                              void* d_out, int out_size) {
    const float* x   = (const float*)d_in[0];
    const int*   idx = (const int*)  d_in[1];
    const float* w   = (const float*)d_in[2];
    float* out = (float*)d_out;

    const long long TH  = (long long)T * H;          // 16,777,216
    const long long TKH = (long long)TK * H;         // 134,217,728
    const long long os  = (long long)out_size;

    float* comb = nullptr;
    float* disp = nullptr;
    float* tpe  = nullptr;

    if (os >= TH + TKH) {
        comb = out;
        disp = out + TH;
        if (os >= TH + TKH + E) tpe = out + TH + TKH;
    } else if (os == TKH) {
        disp = out;                                  // dispatched-only layout
    } else {
        comb = out;                                  // combined-only layout
    }

    k_fused<<<NTOT, 256>>>((const float4*)x, w, idx,
                           (float4*)comb, (float4*)disp, tpe);
}